// round 4
// baseline (speedup 1.0000x reference)
#include <cuda_runtime.h>
#include <cuda_bf16.h>

// Shapes are fixed by the problem instance.
#define Bb 8
#define Cc 256
#define Hh 224
#define Ww 224
#define HW (Hh * Ww)            // 50176
#define PIX_PER_BLK 1024        // 256 threads * float4
#define NCHUNK (HW / PIX_PER_BLK) // 49
#define RSTRIP 16               // rows per K3 block (224/16 = 14 strips)

// Scratch (allocation-free: __device__ globals)
__device__ float g_partial[NCHUNK * Bb * Cc];  // per-chunk channel sums
__device__ float g_S[Bb * HW];                 // sigmoided spatial gate
__device__ float g_ch[Bb * Cc];                // sigmoided channel gate

__device__ __forceinline__ float fsigmoid(float v) {
    return 1.0f / (1.0f + __expf(-v));
}

// ---------------------------------------------------------------------------
// K1: per-pixel channel dot (spatial gate) + per-channel partial sums.
// grid = (NCHUNK, B), block = 256
// ---------------------------------------------------------------------------
__global__ __launch_bounds__(256) void k1_spatial_and_sums(
    const float* __restrict__ x,
    const float* __restrict__ spatial_w,
    const float* __restrict__ spatial_b)
{
    __shared__ float s_w[Cc];
    __shared__ float s_wsum[8][Cc];   // per-warp channel partials

    const int tid  = threadIdx.x;
    const int warp = tid >> 5;
    const int lane = tid & 31;
    const int chunk = blockIdx.x;
    const int b     = blockIdx.y;

    s_w[tid] = spatial_w[tid];   // C == 256 == blockDim
    __syncthreads();

    const float4* xb = reinterpret_cast<const float4*>(
        x + (size_t)b * Cc * HW + (size_t)chunk * PIX_PER_BLK);
    const int ch_stride4 = HW / 4;   // float4 stride between channels

    float d0 = 0.f, d1 = 0.f, d2 = 0.f, d3 = 0.f;

    #pragma unroll 4
    for (int c = 0; c < Cc; ++c) {
        float4 v = __ldg(&xb[(size_t)c * ch_stride4 + tid]);
        float wv = s_w[c];
        d0 = fmaf(v.x, wv, d0);
        d1 = fmaf(v.y, wv, d1);
        d2 = fmaf(v.z, wv, d2);
        d3 = fmaf(v.w, wv, d3);
        float cs = (v.x + v.y) + (v.z + v.w);
        cs += __shfl_down_sync(0xFFFFFFFFu, cs, 16);
        cs += __shfl_down_sync(0xFFFFFFFFu, cs, 8);
        cs += __shfl_down_sync(0xFFFFFFFFu, cs, 4);
        cs += __shfl_down_sync(0xFFFFFFFFu, cs, 2);
        cs += __shfl_down_sync(0xFFFFFFFFu, cs, 1);
        if (lane == 0) s_wsum[warp][c] = cs;
    }
    __syncthreads();

    // Deterministic cross-warp reduce -> per-chunk partial channel sum
    {
        float s = 0.f;
        #pragma unroll
        for (int w = 0; w < 8; ++w) s += s_wsum[w][tid];
        g_partial[(chunk * Bb + b) * Cc + tid] = s;
    }

    // Sigmoided spatial gate
    const float sb = spatial_b[0];
    float4 g;
    g.x = fsigmoid(d0 + sb);
    g.y = fsigmoid(d1 + sb);
    g.z = fsigmoid(d2 + sb);
    g.w = fsigmoid(d3 + sb);
    float4* Sg = reinterpret_cast<float4*>(g_S + (size_t)b * HW + (size_t)chunk * PIX_PER_BLK);
    Sg[tid] = g;
}

// ---------------------------------------------------------------------------
// K2: reduce partials -> avg -> relu MLP -> sigmoid channel gate.
// grid = B, block = 256
// ---------------------------------------------------------------------------
__global__ __launch_bounds__(256) void k2_channel_gate(
    const float* __restrict__ cc1_w,  // [64, 256]
    const float* __restrict__ cc1_b,  // [64]
    const float* __restrict__ cc2_w,  // [256, 64]
    const float* __restrict__ cc2_b)  // [256]
{
    __shared__ float s_avg[Cc];
    __shared__ float s_hid[Cc / 4];

    const int b   = blockIdx.x;
    const int tid = threadIdx.x;

    float s = 0.f;
    for (int ch = 0; ch < NCHUNK; ++ch)
        s += g_partial[(ch * Bb + b) * Cc + tid];
    s_avg[tid] = s * (1.0f / (float)HW);
    __syncthreads();

    if (tid < Cc / 4) {
        float acc = cc1_b[tid];
        const float* wrow = cc1_w + tid * Cc;
        #pragma unroll 4
        for (int c = 0; c < Cc; ++c) acc = fmaf(s_avg[c], wrow[c], acc);
        s_hid[tid] = fmaxf(acc, 0.f);
    }
    __syncthreads();

    float acc = cc2_b[tid];
    const float* wrow = cc2_w + tid * (Cc / 4);
    #pragma unroll
    for (int j = 0; j < Cc / 4; ++j) acc = fmaf(s_hid[j], wrow[j], acc);
    g_ch[b * Cc + tid] = fsigmoid(acc);
}

// ---------------------------------------------------------------------------
// K3: depthwise 3x3 Sobel (9*center - boxsum) + fused gating + write.
// grid = (14 strips, B*C planes), block = 224 (one thread per column)
// ---------------------------------------------------------------------------
__global__ __launch_bounds__(224) void k3_edge_and_gate(
    const float* __restrict__ x,
    float* __restrict__ out)
{
    __shared__ float s[RSTRIP + 2][Ww + 2];   // 18 x 226, zero halo

    const int tid   = threadIdx.x;            // column 0..223
    const int plane = blockIdx.y;             // b*C + c
    const int strip = blockIdx.x;
    const int h0    = strip * RSTRIP;
    const int b     = plane >> 8;

    const float* xp = x + (size_t)plane * HW;

    // Cooperative tile load with zero padding (rows h0-1 .. h0+16, cols -1..224)
    for (int i = tid; i < (RSTRIP + 2) * (Ww + 2); i += 224) {
        int r  = i / (Ww + 2);
        int cc = i - r * (Ww + 2);
        int gh = h0 - 1 + r;
        int gw = cc - 1;
        float v = 0.f;
        if ((unsigned)gh < (unsigned)Hh && (unsigned)gw < (unsigned)Ww)
            v = __ldg(&xp[gh * Ww + gw]);
        s[r][cc] = v;
    }
    __syncthreads();

    const float ch = g_ch[plane];

    // Column triple sums (sliding window over rows)
    float t[RSTRIP + 2];
    #pragma unroll
    for (int r = 0; r < RSTRIP + 2; ++r)
        t[r] = s[r][tid] + s[r][tid + 1] + s[r][tid + 2];

    const float* Sg = g_S + (size_t)b * HW + (size_t)h0 * Ww + tid;
    float*       op = out + (size_t)plane * HW + (size_t)h0 * Ww + tid;

    #pragma unroll
    for (int r = 0; r < RSTRIP; ++r) {
        float center = s[r + 1][tid + 1];
        float box    = (t[r] + t[r + 1]) + t[r + 2];
        float edge   = fmaf(9.f, center, -box);          // 8*c - (box - c)
        float eg     = fsigmoid(edge);
        float sg     = Sg[r * Ww];
        op[r * Ww]   = center * (sg * ch * eg);
    }
}

// ---------------------------------------------------------------------------
extern "C" void kernel_launch(void* const* d_in, const int* in_sizes, int n_in,
                              void* d_out, int out_size)
{
    const float* x         = (const float*)d_in[0];
    const float* spatial_w = (const float*)d_in[1];
    const float* spatial_b = (const float*)d_in[2];
    const float* cc1_w     = (const float*)d_in[3];
    const float* cc1_b     = (const float*)d_in[4];
    const float* cc2_w     = (const float*)d_in[5];
    const float* cc2_b     = (const float*)d_in[6];
    float* out             = (float*)d_out;

    dim3 g1(NCHUNK, Bb);
    k1_spatial_and_sums<<<g1, 256>>>(x, spatial_w, spatial_b);

    k2_channel_gate<<<Bb, 256>>>(cc1_w, cc1_b, cc2_w, cc2_b);

    dim3 g3(Hh / RSTRIP, Bb * Cc);
    k3_edge_and_gate<<<g3, 224>>>(x, out);
}

// round 5
// speedup vs baseline: 1.6397x; 1.6397x over previous
#include <cuda_runtime.h>
#include <cuda_bf16.h>

#define Bb 8
#define Cc 256
#define Hh 224
#define Ww 224
#define HW (Hh * Ww)              // 50176
#define PIX_PER_BLK 1024
#define NCHUNK (HW / PIX_PER_BLK) // 49
#define CHALF 128                 // channels per K1 block (C split in 2)
#define RS 56                     // rows per K3 block (224/56 = 4 strips)

// Scratch (__device__ globals: allocation-free)
__device__ float g_partial[NCHUNK * Bb * Cc]; // per-chunk channel sums
__device__ float g_dot[2 * Bb * HW];          // partial spatial dots (2 halves)
__device__ float g_S[Bb * HW];                // sigmoided spatial gate
__device__ float g_ch[Bb * Cc];               // sigmoided channel gate

__device__ __forceinline__ float fsigmoid(float v) {
    return __fdividef(1.0f, 1.0f + __expf(-v));
}

// ---------------------------------------------------------------------------
// K1: half-channel spatial dot partials + per-channel sums.
// grid = (NCHUNK, B, 2), block = 256
// ---------------------------------------------------------------------------
__global__ __launch_bounds__(256) void k1_spatial_and_sums(
    const float* __restrict__ x,
    const float* __restrict__ spatial_w)
{
    __shared__ float s_w[CHALF];
    __shared__ float s_wsum[8][CHALF];

    const int tid  = threadIdx.x;
    const int warp = tid >> 5;
    const int lane = tid & 31;
    const int chunk = blockIdx.x;
    const int b     = blockIdx.y;
    const int z     = blockIdx.z;

    if (tid < CHALF) s_w[tid] = spatial_w[z * CHALF + tid];
    __syncthreads();

    const float4* xb = reinterpret_cast<const float4*>(
        x + ((size_t)b * Cc + (size_t)z * CHALF) * HW + (size_t)chunk * PIX_PER_BLK);
    const int cs4 = HW / 4;

    float d0 = 0.f, d1 = 0.f, d2 = 0.f, d3 = 0.f;

    #pragma unroll 8
    for (int c = 0; c < CHALF; ++c) {
        float4 v = __ldg(&xb[(size_t)c * cs4 + tid]);
        float wv = s_w[c];
        d0 = fmaf(v.x, wv, d0);
        d1 = fmaf(v.y, wv, d1);
        d2 = fmaf(v.z, wv, d2);
        d3 = fmaf(v.w, wv, d3);
        float cs = (v.x + v.y) + (v.z + v.w);
        cs += __shfl_down_sync(0xFFFFFFFFu, cs, 16);
        cs += __shfl_down_sync(0xFFFFFFFFu, cs, 8);
        cs += __shfl_down_sync(0xFFFFFFFFu, cs, 4);
        cs += __shfl_down_sync(0xFFFFFFFFu, cs, 2);
        cs += __shfl_down_sync(0xFFFFFFFFu, cs, 1);
        if (lane == 0) s_wsum[warp][c] = cs;
    }
    __syncthreads();

    if (tid < CHALF) {
        float s = 0.f;
        #pragma unroll
        for (int w = 0; w < 8; ++w) s += s_wsum[w][tid];
        g_partial[(chunk * Bb + b) * Cc + z * CHALF + tid] = s;
    }

    float4 d = make_float4(d0, d1, d2, d3);
    float4* dp = reinterpret_cast<float4*>(
        g_dot + ((size_t)z * Bb + b) * HW + (size_t)chunk * PIX_PER_BLK);
    dp[tid] = d;
}

// ---------------------------------------------------------------------------
// K1b: combine the 2 dot halves -> sigmoided spatial gate.
// grid = B*HW/4/256 = 392, block = 256
// ---------------------------------------------------------------------------
__global__ __launch_bounds__(256) void k1b_gate(const float* __restrict__ spatial_b)
{
    const int i = blockIdx.x * 256 + threadIdx.x;   // over Bb*HW/4 float4s
    const float sb = spatial_b[0];
    const float4* a = reinterpret_cast<const float4*>(g_dot);
    const float4* c = reinterpret_cast<const float4*>(g_dot + (size_t)Bb * HW);
    float4 u = a[i], v = c[i];
    float4 g;
    g.x = fsigmoid(u.x + v.x + sb);
    g.y = fsigmoid(u.y + v.y + sb);
    g.z = fsigmoid(u.z + v.z + sb);
    g.w = fsigmoid(u.w + v.w + sb);
    reinterpret_cast<float4*>(g_S)[i] = g;
}

// ---------------------------------------------------------------------------
// K2: reduce partials -> avg -> relu MLP -> sigmoid channel gate.
// grid = B, block = 256
// ---------------------------------------------------------------------------
__global__ __launch_bounds__(256) void k2_channel_gate(
    const float* __restrict__ cc1_w,  // [64, 256]
    const float* __restrict__ cc1_b,  // [64]
    const float* __restrict__ cc2_w,  // [256, 64]
    const float* __restrict__ cc2_b)  // [256]
{
    __shared__ float s_avg[Cc];
    __shared__ float s_hid[Cc / 4];

    const int b   = blockIdx.x;
    const int tid = threadIdx.x;

    float s = 0.f;
    for (int ch = 0; ch < NCHUNK; ++ch)
        s += g_partial[(ch * Bb + b) * Cc + tid];
    s_avg[tid] = s * (1.0f / (float)HW);
    __syncthreads();

    if (tid < Cc / 4) {
        float acc = cc1_b[tid];
        const float* wrow = cc1_w + tid * Cc;
        #pragma unroll 4
        for (int c = 0; c < Cc; ++c) acc = fmaf(s_avg[c], wrow[c], acc);
        s_hid[tid] = fmaxf(acc, 0.f);
    }
    __syncthreads();

    float acc = cc2_b[tid];
    const float* wrow = cc2_w + tid * (Cc / 4);
    #pragma unroll
    for (int j = 0; j < Cc / 4; ++j) acc = fmaf(s_hid[j], wrow[j], acc);
    g_ch[b * Cc + tid] = fsigmoid(acc);
}

// ---------------------------------------------------------------------------
// K3: register-sliding 3x3 box stencil + fused gating.
// Warp w owns input columns [30w-1, 30w+30]; lanes 1..30 produce outputs.
// Vertical box via 3-register sliding window down RS rows. No shared memory.
// grid = (H/RS, B*C), block = 256 (8 warps)
// ---------------------------------------------------------------------------
__global__ __launch_bounds__(256) void k3_edge_and_gate(
    const float* __restrict__ x,
    float* __restrict__ out)
{
    const int w   = threadIdx.x >> 5;
    const int l   = threadIdx.x & 31;
    const int col = 30 * w - 1 + l;                       // -1 .. 240
    const bool colok = (unsigned)col < (unsigned)Ww;
    const bool outok = (l >= 1) && (l <= 30) && colok;

    const int plane = blockIdx.y;                          // b*C + c
    const int b     = plane >> 8;
    const int r0    = blockIdx.x * RS;

    const float* xp = x + (size_t)plane * HW;
    const float* gS = g_S + (size_t)b * HW;
    float*       op = out + (size_t)plane * HW;
    const float  K  = __ldg(&g_ch[plane]);

    auto loadx = [&](int r) -> float {
        return (colok && (unsigned)r < (unsigned)Hh) ? __ldg(xp + r * Ww + col) : 0.f;
    };
    auto hsum = [&](float v) -> float {
        float vl = __shfl_up_sync(0xFFFFFFFFu, v, 1);
        float vr = __shfl_down_sync(0xFFFFFFFFu, v, 1);
        return vl + v + vr;   // garbage at lanes 0/31 — never consumed
    };

    float vm = loadx(r0 - 1);
    float h_m = hsum(vm);
    float v_c = loadx(r0);
    float h_c = hsum(v_c);

    #pragma unroll 4
    for (int r = r0; r < r0 + RS; ++r) {
        float v_p = loadx(r + 1);
        float h_p = hsum(v_p);
        float box = (h_m + h_c) + h_p;
        float edge = fmaf(9.f, v_c, -box);   // 8*c - (box - c)
        if (outok) {
            float sg = __ldg(gS + r * Ww + col);
            op[r * Ww + col] = v_c * (sg * K * fsigmoid(edge));
        }
        h_m = h_c; h_c = h_p; v_c = v_p;
    }
}

// ---------------------------------------------------------------------------
extern "C" void kernel_launch(void* const* d_in, const int* in_sizes, int n_in,
                              void* d_out, int out_size)
{
    const float* x         = (const float*)d_in[0];
    const float* spatial_w = (const float*)d_in[1];
    const float* spatial_b = (const float*)d_in[2];
    const float* cc1_w     = (const float*)d_in[3];
    const float* cc1_b     = (const float*)d_in[4];
    const float* cc2_w     = (const float*)d_in[5];
    const float* cc2_b     = (const float*)d_in[6];
    float* out             = (float*)d_out;

    dim3 g1(NCHUNK, Bb, 2);
    k1_spatial_and_sums<<<g1, 256>>>(x, spatial_w);

    k1b_gate<<<(Bb * HW / 4) / 256, 256>>>(spatial_b);

    k2_channel_gate<<<Bb, 256>>>(cc1_w, cc1_b, cc2_w, cc2_b);

    dim3 g3(Hh / RS, Bb * Cc);
    k3_edge_and_gate<<<g3, 256>>>(x, out);
}

// round 6
// speedup vs baseline: 2.5570x; 1.5594x over previous
#include <cuda_runtime.h>
#include <cuda_bf16.h>

#define Bb 8
#define Cc 256
#define Hh 224
#define Ww 224
#define HW (Hh * Ww)              // 50176
#define PIX_PER_BLK 1024
#define NCHUNK (HW / PIX_PER_BLK) // 49
#define CHALF 128                 // channels per K1 block (C split in 2)
#define RSEG 14                   // rows per thread in K3
#define NSEG 4                    // row segments per K3 block
#define RS (RSEG * NSEG)          // 56 rows per K3 block

// Scratch (__device__ globals: allocation-free)
__device__ float g_partial[NCHUNK * Bb * Cc]; // per-chunk channel sums
__device__ float g_dot[2 * Bb * HW];          // partial spatial dots (2 halves)
__device__ float g_S[Bb * HW];                // sigmoided spatial gate
__device__ float g_ch[Bb * Cc];               // sigmoided channel gate

__device__ __forceinline__ float fsigmoid(float v) {
    return __fdividef(1.0f, 1.0f + __expf(-v));
}

// ---------------------------------------------------------------------------
// K1: half-channel spatial dot partials + per-channel sums.
// grid = (NCHUNK, B, 2), block = 256
// ---------------------------------------------------------------------------
__global__ __launch_bounds__(256) void k1_spatial_and_sums(
    const float* __restrict__ x,
    const float* __restrict__ spatial_w)
{
    __shared__ float s_w[CHALF];
    __shared__ float s_wsum[8][CHALF];

    const int tid  = threadIdx.x;
    const int warp = tid >> 5;
    const int lane = tid & 31;
    const int chunk = blockIdx.x;
    const int b     = blockIdx.y;
    const int z     = blockIdx.z;

    if (tid < CHALF) s_w[tid] = spatial_w[z * CHALF + tid];
    __syncthreads();

    const float4* xb = reinterpret_cast<const float4*>(
        x + ((size_t)b * Cc + (size_t)z * CHALF) * HW + (size_t)chunk * PIX_PER_BLK);
    const int cs4 = HW / 4;

    float d0 = 0.f, d1 = 0.f, d2 = 0.f, d3 = 0.f;

    #pragma unroll 8
    for (int c = 0; c < CHALF; ++c) {
        float4 v = __ldg(&xb[(size_t)c * cs4 + tid]);
        float wv = s_w[c];
        d0 = fmaf(v.x, wv, d0);
        d1 = fmaf(v.y, wv, d1);
        d2 = fmaf(v.z, wv, d2);
        d3 = fmaf(v.w, wv, d3);
        float cs = (v.x + v.y) + (v.z + v.w);
        cs += __shfl_down_sync(0xFFFFFFFFu, cs, 16);
        cs += __shfl_down_sync(0xFFFFFFFFu, cs, 8);
        cs += __shfl_down_sync(0xFFFFFFFFu, cs, 4);
        cs += __shfl_down_sync(0xFFFFFFFFu, cs, 2);
        cs += __shfl_down_sync(0xFFFFFFFFu, cs, 1);
        if (lane == 0) s_wsum[warp][c] = cs;
    }
    __syncthreads();

    if (tid < CHALF) {
        float s = 0.f;
        #pragma unroll
        for (int w = 0; w < 8; ++w) s += s_wsum[w][tid];
        g_partial[(chunk * Bb + b) * Cc + z * CHALF + tid] = s;
    }

    float4 d = make_float4(d0, d1, d2, d3);
    float4* dp = reinterpret_cast<float4*>(
        g_dot + ((size_t)z * Bb + b) * HW + (size_t)chunk * PIX_PER_BLK);
    dp[tid] = d;
}

// ---------------------------------------------------------------------------
// K1b: combine the 2 dot halves -> sigmoided spatial gate.
// ---------------------------------------------------------------------------
__global__ __launch_bounds__(256) void k1b_gate(const float* __restrict__ spatial_b)
{
    const int i = blockIdx.x * 256 + threadIdx.x;   // over Bb*HW/4 float4s
    const float sb = spatial_b[0];
    const float4* a = reinterpret_cast<const float4*>(g_dot);
    const float4* c = reinterpret_cast<const float4*>(g_dot + (size_t)Bb * HW);
    float4 u = a[i], v = c[i];
    float4 g;
    g.x = fsigmoid(u.x + v.x + sb);
    g.y = fsigmoid(u.y + v.y + sb);
    g.z = fsigmoid(u.z + v.z + sb);
    g.w = fsigmoid(u.w + v.w + sb);
    reinterpret_cast<float4*>(g_S)[i] = g;
}

// ---------------------------------------------------------------------------
// K2: reduce partials -> avg -> relu MLP -> sigmoid channel gate.
// ---------------------------------------------------------------------------
__global__ __launch_bounds__(256) void k2_channel_gate(
    const float* __restrict__ cc1_w,  // [64, 256]
    const float* __restrict__ cc1_b,  // [64]
    const float* __restrict__ cc2_w,  // [256, 64]
    const float* __restrict__ cc2_b)  // [256]
{
    __shared__ float s_avg[Cc];
    __shared__ float s_hid[Cc / 4];

    const int b   = blockIdx.x;
    const int tid = threadIdx.x;

    float s = 0.f;
    for (int ch = 0; ch < NCHUNK; ++ch)
        s += g_partial[(ch * Bb + b) * Cc + tid];
    s_avg[tid] = s * (1.0f / (float)HW);
    __syncthreads();

    if (tid < Cc / 4) {
        float acc = cc1_b[tid];
        const float* wrow = cc1_w + tid * Cc;
        #pragma unroll 4
        for (int c = 0; c < Cc; ++c) acc = fmaf(s_avg[c], wrow[c], acc);
        s_hid[tid] = fmaxf(acc, 0.f);
    }
    __syncthreads();

    float acc = cc2_b[tid];
    const float* wrow = cc2_w + tid * (Cc / 4);
    #pragma unroll
    for (int j = 0; j < Cc / 4; ++j) acc = fmaf(s_hid[j], wrow[j], acc);
    g_ch[b * Cc + tid] = fsigmoid(acc);
}

// ---------------------------------------------------------------------------
// K3 v2: vectorized 3x3 box stencil + fused gating.
// Thread owns a 4-wide column group (float4) and slides a 3-row window down
// RSEG contiguous rows. Halo columns via 2 scalar L1-hit loads. No smem.
// grid = (H/RS, B*C), block = 224 (56 col-groups x 4 row-segments)
// ---------------------------------------------------------------------------
__global__ __launch_bounds__(224) void k3_edge_and_gate(
    const float* __restrict__ x,
    float* __restrict__ out)
{
    const int t   = threadIdx.x;
    const int c4  = t % 56;            // float4 column group 0..55
    const int seg = t / 56;            // row segment 0..3
    const int col = c4 * 4;

    const int plane = blockIdx.y;      // b*C + c
    const int b     = plane >> 8;
    const int rst   = blockIdx.x * RS + seg * RSEG;

    const float* xp = x + (size_t)plane * HW;

    // load one padded row: float4 of own columns + left/right halo scalars
    auto ldrow = [&](int r, float& lf, float& rf) -> float4 {
        if ((unsigned)r >= (unsigned)Hh) {
            lf = 0.f; rf = 0.f;
            return make_float4(0.f, 0.f, 0.f, 0.f);
        }
        const float* row = xp + r * Ww;
        float4 v = __ldg(reinterpret_cast<const float4*>(row + col));
        lf = (c4 > 0)  ? __ldg(row + col - 1) : 0.f;
        rf = (c4 < 55) ? __ldg(row + col + 4) : 0.f;
        return v;
    };
    // horizontal triple-sums for the 4 output columns
    auto hs = [](float4 v, float l, float r) -> float4 {
        float t1 = v.x + v.y;
        float t2 = v.z + v.w;
        return make_float4(l + t1, t1 + v.z, v.y + t2, t2 + r);
    };

    float lf, rf;
    float4 vA = ldrow(rst - 1, lf, rf);
    float4 hm = hs(vA, lf, rf);
    float4 vc = ldrow(rst, lf, rf);
    float4 hc = hs(vc, lf, rf);

    const float K = __ldg(&g_ch[plane]);
    const float* gSp = g_S + (size_t)b * HW + (size_t)rst * Ww + col;
    float*       op  = out + (size_t)plane * HW + (size_t)rst * Ww + col;

    #pragma unroll
    for (int i = 0; i < RSEG; ++i) {
        float4 vp = ldrow(rst + i + 1, lf, rf);
        float4 hp = hs(vp, lf, rf);
        float4 sg = __ldg(reinterpret_cast<const float4*>(gSp + i * Ww));

        float4 o;
        o.x = vc.x * (sg.x * K * fsigmoid(fmaf(9.f, vc.x, -((hm.x + hc.x) + hp.x))));
        o.y = vc.y * (sg.y * K * fsigmoid(fmaf(9.f, vc.y, -((hm.y + hc.y) + hp.y))));
        o.z = vc.z * (sg.z * K * fsigmoid(fmaf(9.f, vc.z, -((hm.z + hc.z) + hp.z))));
        o.w = vc.w * (sg.w * K * fsigmoid(fmaf(9.f, vc.w, -((hm.w + hc.w) + hp.w))));
        *reinterpret_cast<float4*>(op + i * Ww) = o;

        hm = hc; hc = hp; vc = vp;
    }
}

// ---------------------------------------------------------------------------
extern "C" void kernel_launch(void* const* d_in, const int* in_sizes, int n_in,
                              void* d_out, int out_size)
{
    const float* x         = (const float*)d_in[0];
    const float* spatial_w = (const float*)d_in[1];
    const float* spatial_b = (const float*)d_in[2];
    const float* cc1_w     = (const float*)d_in[3];
    const float* cc1_b     = (const float*)d_in[4];
    const float* cc2_w     = (const float*)d_in[5];
    const float* cc2_b     = (const float*)d_in[6];
    float* out             = (float*)d_out;

    dim3 g1(NCHUNK, Bb, 2);
    k1_spatial_and_sums<<<g1, 256>>>(x, spatial_w);

    k1b_gate<<<(Bb * HW / 4) / 256, 256>>>(spatial_b);

    k2_channel_gate<<<Bb, 256>>>(cc1_w, cc1_b, cc2_w, cc2_b);

    dim3 g3(Hh / RS, Bb * Cc);
    k3_edge_and_gate<<<g3, 224>>>(x, out);
}